// round 15
// baseline (speedup 1.0000x reference)
#include <cuda_runtime.h>
#include <math.h>

#define NPERROW (512*512)            // 262144
#define NROWS   128
#define NV4     (NPERROW/4)          // 65536
#define FULLM   0xFFFFFFFFu
#define NORANK  0xFFFFFFFFu

#define CHUNKS  16
#define NTASK   (NROWS*CHUNKS)       // 2048
#define PTH     256
#define V4C     (NV4/CHUNKS)         // 4096 float4 per chunk
#define V4T     (V4C/PTH)            // 16 float4 per thread
#define NW      (PTH/32)             // 8 warps
#define TCAP    24                   // per-thread stage cap (exp ~3)
#define CSEG    1024                 // per-chunk segment cap (exp ~746)
#define MCAP    (CHUNKS*CSEG)        // 16384
#define CCAPS   1536                 // candidate cap (exp ~900)
#define SMW     (TCAP*PTH)           // 6144 words = 24 KB arena

__device__ unsigned int g_buf[NROWS][MCAP];    // 8 MB scratch
__device__ unsigned int g_ccnt[NROWS][CHUNKS];
__device__ float        g_q[NROWS][2];         // [0]=i1, [1]=i99
__device__ unsigned int g_bar, g_gen;          // device barrier state (self-resetting)

// monotone float -> uint key
__device__ __forceinline__ unsigned int f2k(float f) {
    unsigned int u = __float_as_uint(f);
    return u ^ ((unsigned int)((int)u >> 31) | 0x80000000u);
}
__device__ __forceinline__ float k2f(unsigned int k) {
    unsigned int u = (k & 0x80000000u) ? (k ^ 0x80000000u) : ~k;
    return __uint_as_float(u);
}
__device__ __forceinline__ float ex2a(float x){ float r; asm("ex2.approx.ftz.f32 %0, %1;" : "=f"(r) : "f"(x)); return r; }
__device__ __forceinline__ float rcpa(float x){ float r; asm("rcp.approx.ftz.f32 %0, %1;" : "=f"(r) : "f"(x)); return r; }

// device-wide barrier: all gridDim.x CTAs are resident by construction.
__device__ __forceinline__ void grid_barrier() {
    __threadfence();
    __syncthreads();
    if (threadIdx.x == 0) {
        unsigned int gen = *(volatile unsigned int*)&g_gen;   // snapshot BEFORE arriving
        if (atomicAdd(&g_bar, 1u) == gridDim.x - 1u) {
            g_bar = 0u;
            __threadfence();
            atomicAdd(&g_gen, 1u);
        } else {
            while (*(volatile unsigned int*)&g_gen == gen) __nanosleep(64);
        }
    }
    __syncthreads();
    __threadfence();
}

// block scan over h[0..nbins) (nbins multiple of 256); locate lr0 (and lr1 if != NORANK).
// from_top: lr = total - lr_in. Outputs: s_out[0]=bin0,[1]=pre0,[2]=bin1,[3]=pre1,[4]=total.
__device__ void scanloc(unsigned int* h, int nbins,
                        unsigned int lr0_in, unsigned int lr1_in, int from_top,
                        unsigned int* wsum, unsigned int* s_out,
                        int tid, int lane, int wid)
{
    const int bpt = nbins >> 8;
    unsigned int s = 0;
    for (int j = 0; j < bpt; j++) s += h[tid * bpt + j];
    unsigned int inc = s;
    #pragma unroll
    for (int o = 1; o < 32; o <<= 1) {
        unsigned int t = __shfl_up_sync(FULLM, inc, o);
        if (lane >= o) inc += t;
    }
    if (lane == 31) wsum[wid] = inc;
    __syncthreads();
    if (tid < NW) {
        unsigned int w = wsum[tid];
        #pragma unroll
        for (int o = 1; o < NW; o <<= 1) {
            unsigned int t = __shfl_up_sync(0xFFu, w, o);
            if (tid >= o) w += t;
        }
        wsum[tid] = w;
    }
    __syncthreads();
    const unsigned int total = wsum[NW - 1];
    if (tid == 0) s_out[4] = total;
    unsigned int lr0 = from_top ? (total - lr0_in) : lr0_in;
    unsigned int lr1 = (lr1_in == NORANK) ? NORANK : (from_top ? (total - lr1_in) : lr1_in);
    unsigned int run = (wid ? wsum[wid - 1] : 0u) + inc - s;
    for (int j = 0; j < bpt; j++) {
        unsigned int c = h[tid * bpt + j];
        unsigned int b = (unsigned int)(tid * bpt + j);
        if (run <= lr0 && lr0 < run + c) { s_out[0] = b; s_out[1] = run; }
        if (lr1 != NORANK && run <= lr1 && lr1 < run + c) { s_out[2] = b; s_out[3] = run; }
        run += c;
    }
    __syncthreads();
}

__global__ __launch_bounds__(PTH, 5)
void fused_kernel(const float* __restrict__ x, float* __restrict__ out,
                  const float* __restrict__ alpha_p, const float* __restrict__ beta_p)
{
    __shared__ unsigned int sm[SMW];     // gather stage / select hists+candidates
    __shared__ unsigned int wsum[NW];
    __shared__ unsigned int cc[CHUNKS];
    __shared__ unsigned int s_out[5];
    __shared__ unsigned int sb[2], sp[2], b2s[2], p2s[2], keyq[2];
    __shared__ unsigned int s_c;
    __shared__ int s_ov, s_mode;

    const int tid  = threadIdx.x;
    const int lane = tid & 31;
    const int wid  = tid >> 5;

    // ================= Phase 1: gather |x|>2 tails =================
    for (int task = blockIdx.x; task < NTASK; task += gridDim.x) {
        const int row = task >> 4, chk = task & (CHUNKS - 1);
        const float4* xr = (const float4*)(x + (size_t)row * NPERROW) + (size_t)chk * V4C;
        __syncthreads();                 // protect wsum/s_ov reuse across tasks
        if (tid == 0) s_ov = 0;
        __syncthreads();

        unsigned int cnt = 0;
        #pragma unroll
        for (int it = 0; it < V4T / 4; it++) {
            float4 v0 = __ldcs(&xr[tid + (it * 4 + 0) * PTH]);
            float4 v1 = __ldcs(&xr[tid + (it * 4 + 1) * PTH]);
            float4 v2 = __ldcs(&xr[tid + (it * 4 + 2) * PTH]);
            float4 v3 = __ldcs(&xr[tid + (it * 4 + 3) * PTH]);
            float f[16] = {v0.x, v0.y, v0.z, v0.w, v1.x, v1.y, v1.z, v1.w,
                           v2.x, v2.y, v2.z, v2.w, v3.x, v3.y, v3.z, v3.w};
            #pragma unroll
            for (int e = 0; e < 16; e++) {
                if (fabsf(f[e]) > 2.0f) {
                    if (cnt < TCAP) sm[cnt * PTH + tid] = f2k(f[e]);   // per-thread stripe
                    cnt++;
                }
            }
        }
        if (cnt > TCAP) s_ov = 1;       // benign race; ordered by scan barriers

        unsigned int inc = cnt;
        #pragma unroll
        for (int o = 1; o < 32; o <<= 1) {
            unsigned int t = __shfl_up_sync(FULLM, inc, o);
            if (lane >= o) inc += t;
        }
        if (lane == 31) wsum[wid] = inc;
        __syncthreads();
        if (tid < NW) {
            unsigned int w = wsum[tid];
            #pragma unroll
            for (int o = 1; o < NW; o <<= 1) {
                unsigned int t = __shfl_up_sync(0xFFu, w, o);
                if (tid >= o) w += t;
            }
            wsum[tid] = w;
        }
        __syncthreads();

        unsigned int pre   = (wid ? wsum[wid - 1] : 0u) + inc - cnt;
        unsigned int total = wsum[NW - 1];
        int ov = s_ov || (total > CSEG);
        if (!ov) {
            unsigned int* dst = &g_buf[row][chk * CSEG + pre];
            for (unsigned int j = 0; j < cnt; j++) dst[j] = sm[j * PTH + tid];
        }
        if (tid == 0) g_ccnt[row][chk] = ov ? 0xFFFFFFFFu : total;
    }

    grid_barrier();

    // ================= Phase 2: per-(row,side) select =================
    for (int st = blockIdx.x; st < 2 * NROWS; st += gridDim.x) {
        const int row = st >> 1, side = st & 1;
        const unsigned int base = side ? 0xC0000000u : 0u;

        if (tid < CHUNKS) cc[tid] = g_ccnt[row][tid];
        __syncthreads();
        if (tid == 0) {
            int bad = 0;
            #pragma unroll
            for (int c = 0; c < CHUNKS; c++) if (cc[c] > CSEG) bad = 1;
            s_mode = bad;
        }
        __syncthreads();

        unsigned int lr0 = 0, lr1 = 0;

        if (s_mode == 0) {
            // pass 1: 4096-bin hist over rel>>18 (side keys occupy exactly [0,2^30))
            for (int j = tid; j < 4096; j += PTH) sm[j] = 0u;
            __syncthreads();
            for (int i = tid; i < MCAP; i += PTH) {
                if ((unsigned int)(i & (CSEG - 1)) < cc[i >> 10]) {
                    unsigned int k = g_buf[row][i];
                    if (side ? (k >= 0x80000000u) : (k < 0x80000000u))
                        atomicAdd(&sm[(k - base) >> 18], 1u);
                }
            }
            __syncthreads();
            scanloc(sm, 4096, side ? 2623u : 2621u, side ? 2622u : 2622u, side,
                    wsum, s_out, tid, lane, wid);
            if (tid == 0) { sb[0] = s_out[0]; sp[0] = s_out[1]; sb[1] = s_out[2]; sp[1] = s_out[3]; }
            __syncthreads();
            const unsigned int Mside = s_out[4];
            if (Mside < 2623u) { if (tid == 0) s_mode = 1; }
            __syncthreads();

            if (s_mode == 0) {
                lr0 = side ? (Mside - 2623u) : 2621u;
                lr1 = side ? (Mside - 2622u) : 2622u;

                // extraction into sm[4096..]
                if (tid == 0) s_c = 0u;
                __syncthreads();
                const unsigned int blo = sb[0], bhi = sb[1];
                for (int i = tid; i < MCAP; i += PTH) {
                    if ((unsigned int)(i & (CSEG - 1)) < cc[i >> 10]) {
                        unsigned int k = g_buf[row][i];
                        if (side ? (k >= 0x80000000u) : (k < 0x80000000u)) {
                            unsigned int rel = k - base;
                            unsigned int b = rel >> 18;
                            if (b >= blo && b <= bhi) {
                                unsigned int p = atomicAdd(&s_c, 1u);
                                if (p < CCAPS) sm[4096 + p] = rel;
                            }
                        }
                    }
                }
                __syncthreads();
                if (s_c > (unsigned int)CCAPS) { if (tid == 0) s_mode = 1; }
                __syncthreads();
            }

            if (s_mode == 0) {
                const unsigned int nc = s_c;
                unsigned int lrq0 = lr0 - sp[0], lrq1 = lr1 - sp[1];
                #pragma unroll
                for (int q = 0; q < 2; q++) {
                    const unsigned int b  = sb[q];
                    unsigned int lr = q ? lrq1 : lrq0;

                    for (int j = tid; j < 1024; j += PTH) sm[j] = 0u;
                    __syncthreads();
                    for (unsigned int i = tid; i < nc; i += PTH) {
                        unsigned int rel = sm[4096 + i];
                        if ((rel >> 18) == b) atomicAdd(&sm[(rel >> 8) & 1023u], 1u);
                    }
                    __syncthreads();
                    scanloc(sm, 1024, lr, NORANK, 0, wsum, s_out, tid, lane, wid);
                    const unsigned int s1 = s_out[0];
                    lr -= s_out[1];
                    __syncthreads();

                    const unsigned int t18 = (b << 10) | s1;
                    for (int j = tid; j < 256; j += PTH) sm[j] = 0u;
                    __syncthreads();
                    for (unsigned int i = tid; i < nc; i += PTH) {
                        unsigned int rel = sm[4096 + i];
                        if ((rel >> 8) == t18) atomicAdd(&sm[rel & 255u], 1u);
                    }
                    __syncthreads();
                    scanloc(sm, 256, lr, NORANK, 0, wsum, s_out, tid, lane, wid);
                    if (tid == 0) keyq[q] = base + ((b << 18) | (s1 << 8) | s_out[0]);
                    __syncthreads();
                }
            }
        }

        if (s_mode == 1) {
            // exact full-row fallback: 11/11/10-bit radix for this side's 2 ranks
            const float4* xr = (const float4*)(x + (size_t)row * NPERROW);
            const unsigned int R0 = side ? 259521u : 2621u;
            const unsigned int R1 = R0 + 1u;

            for (int j = tid; j < 2048; j += PTH) sm[j] = 0u;
            __syncthreads();
            for (int i = tid; i < NV4; i += PTH) {
                float4 v = __ldcs(&xr[i]);
                atomicAdd(&sm[f2k(v.x) >> 21], 1u);
                atomicAdd(&sm[f2k(v.y) >> 21], 1u);
                atomicAdd(&sm[f2k(v.z) >> 21], 1u);
                atomicAdd(&sm[f2k(v.w) >> 21], 1u);
            }
            __syncthreads();
            scanloc(sm, 2048, R0, R1, 0, wsum, s_out, tid, lane, wid);
            if (tid == 0) { sb[0] = s_out[0]; sp[0] = s_out[1]; sb[1] = s_out[2]; sp[1] = s_out[3]; }
            __syncthreads();

            for (int j = tid; j < 4096; j += PTH) sm[j] = 0u;
            __syncthreads();
            {
                const unsigned int b0 = sb[0], b1 = sb[1];
                for (int i = tid; i < NV4; i += PTH) {
                    float4 v = __ldcs(&xr[i]);
                    unsigned int ks[4] = {f2k(v.x), f2k(v.y), f2k(v.z), f2k(v.w)};
                    #pragma unroll
                    for (int e = 0; e < 4; e++) {
                        unsigned int t1 = ks[e] >> 21, sub = (ks[e] >> 10) & 2047u;
                        if (t1 == b0) atomicAdd(&sm[sub], 1u);
                        if (t1 == b1) atomicAdd(&sm[2048 + sub], 1u);
                    }
                }
            }
            __syncthreads();
            scanloc(sm,        2048, R0 - sp[0], NORANK, 0, wsum, s_out, tid, lane, wid);
            if (tid == 0) { b2s[0] = s_out[0]; p2s[0] = s_out[1]; }
            __syncthreads();
            scanloc(sm + 2048, 2048, R1 - sp[1], NORANK, 0, wsum, s_out, tid, lane, wid);
            if (tid == 0) { b2s[1] = s_out[0]; p2s[1] = s_out[1]; }
            __syncthreads();

            for (int j = tid; j < 2048; j += PTH) sm[j] = 0u;
            __syncthreads();
            {
                const unsigned int t0 = (sb[0] << 11) | b2s[0];
                const unsigned int t1 = (sb[1] << 11) | b2s[1];
                for (int i = tid; i < NV4; i += PTH) {
                    float4 v = __ldcs(&xr[i]);
                    unsigned int ks[4] = {f2k(v.x), f2k(v.y), f2k(v.z), f2k(v.w)};
                    #pragma unroll
                    for (int e = 0; e < 4; e++) {
                        unsigned int tt = ks[e] >> 10, sub = ks[e] & 1023u;
                        if (tt == t0) atomicAdd(&sm[sub], 1u);
                        if (tt == t1) atomicAdd(&sm[1024 + sub], 1u);
                    }
                }
            }
            __syncthreads();
            scanloc(sm,        1024, R0 - sp[0] - p2s[0], NORANK, 0, wsum, s_out, tid, lane, wid);
            if (tid == 0) keyq[0] = (sb[0] << 21) | (b2s[0] << 10) | s_out[0];
            __syncthreads();
            scanloc(sm + 1024, 1024, R1 - sp[1] - p2s[1], NORANK, 0, wsum, s_out, tid, lane, wid);
            if (tid == 0) keyq[1] = (sb[1] << 21) | (b2s[1] << 10) | s_out[0];
            __syncthreads();
        }

        if (tid == 0) {
            double frac = side ? (0.99 * (double)(NPERROW - 1) - 259521.0)
                               : (0.01 * (double)(NPERROW - 1) - 2621.0);
            double v0 = (double)k2f(keyq[0]);
            double v1 = (double)k2f(keyq[1]);
            g_q[row][side] = (float)(v0 + frac * (v1 - v0));
        }
        __syncthreads();
    }

    grid_barrier();

    // ================= Phase 3: streaming gate =================
    const float alpha = alpha_p[0];
    const float beta  = beta_p[0];
    const float L2E   = 1.4426950408889634f;
    for (int task = blockIdx.x; task < NTASK; task += gridDim.x) {
        const int row = task >> 4, chk = task & (CHUNKS - 1);
        const float4* xr   = (const float4*)(x   + (size_t)row * NPERROW) + (size_t)chk * V4C;
        float4*       outr = (float4*)      (out + (size_t)row * NPERROW) + (size_t)chk * V4C;

        const double i1  = (double)g_q[row][0];
        const double i99 = (double)g_q[row][1];
        const float th = (float)(i1 + (i99 - i1) * (double)alpha);
        const float mask   = (th > 1e-14f) ? 1.0f : 0.0f;
        const float th_new = th * mask + (1.0f - mask);
        const float scale  = beta / th_new;
        const float t      = th * mask;
        const float a = scale * L2E;      // exp(-(scale*(|x|-t))) = 2^(-a*|x| + b)
        const float b = scale * t * L2E;

        #pragma unroll 4
        for (int i = tid; i < V4C; i += PTH) {
            float4 v = __ldcs(&xr[i]);
            float4 o;
            o.x = fmaxf(v.x, 0.0f) * rcpa(1.0f + ex2a(fmaf(fabsf(v.x), -a, b)));
            o.y = fmaxf(v.y, 0.0f) * rcpa(1.0f + ex2a(fmaf(fabsf(v.y), -a, b)));
            o.z = fmaxf(v.z, 0.0f) * rcpa(1.0f + ex2a(fmaf(fabsf(v.z), -a, b)));
            o.w = fmaxf(v.w, 0.0f) * rcpa(1.0f + ex2a(fmaf(fabsf(v.w), -a, b)));
            __stcs(&outr[i], o);
        }
    }
}

extern "C" void kernel_launch(void* const* d_in, const int* in_sizes, int n_in,
                              void* d_out, int out_size)
{
    const float* x     = (const float*)d_in[0];
    const float* alpha = (const float*)d_in[1];
    const float* beta  = (const float*)d_in[2];
    float* out = (float*)d_out;

    // Guaranteed-resident grid (deterministic per device; no allocs, capture-safe)
    int dev = 0;
    cudaGetDevice(&dev);
    int nsm = 0;
    cudaDeviceGetAttribute(&nsm, cudaDevAttrMultiProcessorCount, dev);
    int occ = 0;
    cudaOccupancyMaxActiveBlocksPerMultiprocessor(&occ, fused_kernel, PTH, 0);
    int cap = nsm * occ;
    int grid = (cap >= 1024) ? 1024 : (cap >= 512) ? 512 : (cap >= 256) ? 256
             : (cap >= 128) ? 128 : (cap >= 1) ? cap : 1;

    fused_kernel<<<grid, PTH>>>(x, out, alpha, beta);
}

// round 16
// speedup vs baseline: 1.1084x; 1.1084x over previous
#include <cuda_runtime.h>
#include <math.h>

#define NPERROW (512*512)            // 262144
#define NROWS   128
#define NV4     (NPERROW/4)          // 65536
#define FULLM   0xFFFFFFFFu
#define NORANK  0xFFFFFFFFu

#define CHUNKS  16
#define GTH     256
#define V4C     (NV4/CHUNKS)         // 4096 float4 per chunk
#define V4T     (V4C/GTH)            // 16 float4 per thread
#define NW      (GTH/32)             // 8 warps
#define TCAP    24                   // per-thread stage cap (exp ~3)
#define CSEG    1024                 // per-chunk segment cap (exp ~746)
#define MCAP    (CHUNKS*CSEG)        // 16384
#define CCAPS   1536                 // candidate cap (exp ~900)
#define NSEL    (2*NROWS)            // 256 select CTAs

__device__ unsigned int g_buf[NROWS][MCAP];    // 8 MB scratch
__device__ unsigned int g_ccnt[NROWS][CHUNKS];
__device__ float        g_q[NROWS][2];         // [0]=i1, [1]=i99
__device__ unsigned int g_qready[NROWS];       // reset by gather each replay

// monotone float -> uint key
__device__ __forceinline__ unsigned int f2k(float f) {
    unsigned int u = __float_as_uint(f);
    return u ^ ((unsigned int)((int)u >> 31) | 0x80000000u);
}
__device__ __forceinline__ float k2f(unsigned int k) {
    unsigned int u = (k & 0x80000000u) ? (k ^ 0x80000000u) : ~k;
    return __uint_as_float(u);
}
__device__ __forceinline__ float ex2a(float x){ float r; asm("ex2.approx.ftz.f32 %0, %1;" : "=f"(r) : "f"(x)); return r; }
__device__ __forceinline__ float rcpa(float x){ float r; asm("rcp.approx.ftz.f32 %0, %1;" : "=f"(r) : "f"(x)); return r; }

// ===================== Kernel 1: wide tail gather (R14-proven) =====================
__global__ __launch_bounds__(GTH)
void gather_kernel(const float* __restrict__ x)
{
    __shared__ unsigned int stage[TCAP * GTH];
    __shared__ unsigned int wsum[NW];
    __shared__ int s_ov;

    const int tid  = threadIdx.x;
    const int lane = tid & 31;
    const int wid  = tid >> 5;
    const int row  = blockIdx.x >> 4;
    const int chk  = blockIdx.x & (CHUNKS - 1);
    const float4* xr = (const float4*)(x + (size_t)row * NPERROW) + (size_t)chk * V4C;

    if (tid == 0) {
        s_ov = 0;
        if (chk == 0) g_qready[row] = 0u;   // reset for this replay (K2 runs after K1)
    }
    __syncthreads();

    unsigned int cnt = 0;
    #pragma unroll
    for (int it = 0; it < V4T / 8; it++) {
        float4 v[8];
        #pragma unroll
        for (int s = 0; s < 8; s++)
            v[s] = xr[tid + (it * 8 + s) * GTH];

        #pragma unroll
        for (int s = 0; s < 8; s++) {
            if (fabsf(v[s].x) > 2.0f) { if (cnt < TCAP) stage[cnt * GTH + tid] = f2k(v[s].x); cnt++; }
            if (fabsf(v[s].y) > 2.0f) { if (cnt < TCAP) stage[cnt * GTH + tid] = f2k(v[s].y); cnt++; }
            if (fabsf(v[s].z) > 2.0f) { if (cnt < TCAP) stage[cnt * GTH + tid] = f2k(v[s].z); cnt++; }
            if (fabsf(v[s].w) > 2.0f) { if (cnt < TCAP) stage[cnt * GTH + tid] = f2k(v[s].w); cnt++; }
        }
    }
    if (cnt > TCAP) s_ov = 1;   // benign race; ordered by barriers below

    unsigned int inc = cnt;
    #pragma unroll
    for (int o = 1; o < 32; o <<= 1) {
        unsigned int t = __shfl_up_sync(FULLM, inc, o);
        if (lane >= o) inc += t;
    }
    if (lane == 31) wsum[wid] = inc;
    __syncthreads();
    if (tid < NW) {
        unsigned int w = wsum[tid];
        #pragma unroll
        for (int o = 1; o < NW; o <<= 1) {
            unsigned int t = __shfl_up_sync(0xFFu, w, o);
            if (tid >= o) w += t;
        }
        wsum[tid] = w;
    }
    __syncthreads();

    unsigned int pre   = (wid ? wsum[wid - 1] : 0u) + inc - cnt;
    unsigned int total = wsum[NW - 1];
    int ov = s_ov || (total > CSEG);

    if (!ov) {
        unsigned int* dst = &g_buf[row][chk * CSEG + pre];
        for (unsigned int j = 0; j < cnt; j++) dst[j] = stage[j * GTH + tid];
    }
    if (tid == 0) g_ccnt[row][chk] = ov ? 0xFFFFFFFFu : total;
}

// ===================== Kernel 2: select CTAs + spin-waiting gate CTAs =====================

// block scan over h[0..nbins) (nbins multiple of 256); locate lr0 (and lr1 if != NORANK).
// from_top: lr = total - lr_in. Outputs: s_out[0]=bin0,[1]=pre0,[2]=bin1,[3]=pre1,[4]=total.
__device__ void scanloc(unsigned int* h, int nbins,
                        unsigned int lr0_in, unsigned int lr1_in, int from_top,
                        unsigned int* wsum, unsigned int* s_out,
                        int tid, int lane, int wid)
{
    const int bpt = nbins >> 8;
    unsigned int s = 0;
    for (int j = 0; j < bpt; j++) s += h[tid * bpt + j];
    unsigned int inc = s;
    #pragma unroll
    for (int o = 1; o < 32; o <<= 1) {
        unsigned int t = __shfl_up_sync(FULLM, inc, o);
        if (lane >= o) inc += t;
    }
    if (lane == 31) wsum[wid] = inc;
    __syncthreads();
    if (tid < NW) {
        unsigned int w = wsum[tid];
        #pragma unroll
        for (int o = 1; o < NW; o <<= 1) {
            unsigned int t = __shfl_up_sync(0xFFu, w, o);
            if (tid >= o) w += t;
        }
        wsum[tid] = w;
    }
    __syncthreads();
    const unsigned int total = wsum[NW - 1];
    if (tid == 0) s_out[4] = total;
    unsigned int lr0 = from_top ? (total - lr0_in) : lr0_in;
    unsigned int lr1 = (lr1_in == NORANK) ? NORANK : (from_top ? (total - lr1_in) : lr1_in);
    unsigned int run = (wid ? wsum[wid - 1] : 0u) + inc - s;
    for (int j = 0; j < bpt; j++) {
        unsigned int c = h[tid * bpt + j];
        unsigned int b = (unsigned int)(tid * bpt + j);
        if (run <= lr0 && lr0 < run + c) { s_out[0] = b; s_out[1] = run; }
        if (lr1 != NORANK && run <= lr1 && lr1 < run + c) { s_out[2] = b; s_out[3] = run; }
        run += c;
    }
    __syncthreads();
}

__global__ __launch_bounds__(GTH)
void selgate_kernel(const float* __restrict__ x, float* __restrict__ out,
                    const float* __restrict__ alpha_p, const float* __restrict__ beta_p)
{
    __shared__ unsigned int sm[4096 + CCAPS];   // hist arena + candidates (22.5 KB)
    __shared__ unsigned int wsum[NW];
    __shared__ unsigned int cc[CHUNKS];
    __shared__ unsigned int s_out[5];
    __shared__ unsigned int sb[2], sp[2], b2s[2], p2s[2], keyq[2];
    __shared__ unsigned int s_c;
    __shared__ int s_mode;
    __shared__ float s_th[2];

    const int tid  = threadIdx.x;
    const int lane = tid & 31;
    const int wid  = tid >> 5;

    if (blockIdx.x < NSEL) {
        // ==================== SELECT CTA: (row, side) ====================
        const int row  = blockIdx.x >> 1;
        const int side = blockIdx.x & 1;
        const unsigned int base = side ? 0xC0000000u : 0u;

        if (tid < CHUNKS) cc[tid] = g_ccnt[row][tid];
        __syncthreads();
        if (tid == 0) {
            int bad = 0;
            #pragma unroll
            for (int c = 0; c < CHUNKS; c++) if (cc[c] > CSEG) bad = 1;
            s_mode = bad;
        }
        __syncthreads();

        unsigned int lr0 = 0, lr1 = 0;

        if (s_mode == 0) {
            // pass 1: 4096-bin hist over rel>>18 (side keys occupy exactly [0,2^30))
            for (int j = tid; j < 4096; j += GTH) sm[j] = 0u;
            __syncthreads();
            for (int i = tid; i < MCAP; i += GTH) {
                if ((unsigned int)(i & (CSEG - 1)) < cc[i >> 10]) {
                    unsigned int k = g_buf[row][i];
                    if (side ? (k >= 0x80000000u) : (k < 0x80000000u))
                        atomicAdd(&sm[(k - base) >> 18], 1u);
                }
            }
            __syncthreads();
            scanloc(sm, 4096, side ? 2623u : 2621u, side ? 2622u : 2622u, side,
                    wsum, s_out, tid, lane, wid);
            if (tid == 0) { sb[0] = s_out[0]; sp[0] = s_out[1]; sb[1] = s_out[2]; sp[1] = s_out[3]; }
            __syncthreads();
            const unsigned int Mside = s_out[4];
            if (Mside < 2623u) { if (tid == 0) s_mode = 1; }
            __syncthreads();

            if (s_mode == 0) {
                lr0 = side ? (Mside - 2623u) : 2621u;
                lr1 = side ? (Mside - 2622u) : 2622u;

                if (tid == 0) s_c = 0u;
                __syncthreads();
                const unsigned int blo = sb[0], bhi = sb[1];
                for (int i = tid; i < MCAP; i += GTH) {
                    if ((unsigned int)(i & (CSEG - 1)) < cc[i >> 10]) {
                        unsigned int k = g_buf[row][i];
                        if (side ? (k >= 0x80000000u) : (k < 0x80000000u)) {
                            unsigned int rel = k - base;
                            unsigned int b = rel >> 18;
                            if (b >= blo && b <= bhi) {
                                unsigned int p = atomicAdd(&s_c, 1u);
                                if (p < CCAPS) sm[4096 + p] = rel;
                            }
                        }
                    }
                }
                __syncthreads();
                if (s_c > (unsigned int)CCAPS) { if (tid == 0) s_mode = 1; }
                __syncthreads();
            }

            if (s_mode == 0) {
                const unsigned int nc = s_c;
                unsigned int lrq0 = lr0 - sp[0], lrq1 = lr1 - sp[1];
                #pragma unroll
                for (int q = 0; q < 2; q++) {
                    const unsigned int b = sb[q];
                    unsigned int lr = q ? lrq1 : lrq0;

                    for (int j = tid; j < 1024; j += GTH) sm[j] = 0u;
                    __syncthreads();
                    for (unsigned int i = tid; i < nc; i += GTH) {
                        unsigned int rel = sm[4096 + i];
                        if ((rel >> 18) == b) atomicAdd(&sm[(rel >> 8) & 1023u], 1u);
                    }
                    __syncthreads();
                    scanloc(sm, 1024, lr, NORANK, 0, wsum, s_out, tid, lane, wid);
                    const unsigned int s1 = s_out[0];
                    lr -= s_out[1];
                    __syncthreads();

                    const unsigned int t18 = (b << 10) | s1;
                    for (int j = tid; j < 256; j += GTH) sm[j] = 0u;
                    __syncthreads();
                    for (unsigned int i = tid; i < nc; i += GTH) {
                        unsigned int rel = sm[4096 + i];
                        if ((rel >> 8) == t18) atomicAdd(&sm[rel & 255u], 1u);
                    }
                    __syncthreads();
                    scanloc(sm, 256, lr, NORANK, 0, wsum, s_out, tid, lane, wid);
                    if (tid == 0) keyq[q] = base + ((b << 18) | (s1 << 8) | s_out[0]);
                    __syncthreads();
                }
            }
        }

        if (s_mode == 1) {
            // exact full-row fallback: 11/11/10-bit radix for this side's 2 ranks
            const float4* xr = (const float4*)(x + (size_t)row * NPERROW);
            const unsigned int R0 = side ? 259521u : 2621u;
            const unsigned int R1 = R0 + 1u;

            for (int j = tid; j < 2048; j += GTH) sm[j] = 0u;
            __syncthreads();
            for (int i = tid; i < NV4; i += GTH) {
                float4 v = __ldcs(&xr[i]);
                atomicAdd(&sm[f2k(v.x) >> 21], 1u);
                atomicAdd(&sm[f2k(v.y) >> 21], 1u);
                atomicAdd(&sm[f2k(v.z) >> 21], 1u);
                atomicAdd(&sm[f2k(v.w) >> 21], 1u);
            }
            __syncthreads();
            scanloc(sm, 2048, R0, R1, 0, wsum, s_out, tid, lane, wid);
            if (tid == 0) { sb[0] = s_out[0]; sp[0] = s_out[1]; sb[1] = s_out[2]; sp[1] = s_out[3]; }
            __syncthreads();

            for (int j = tid; j < 4096; j += GTH) sm[j] = 0u;
            __syncthreads();
            {
                const unsigned int b0 = sb[0], b1 = sb[1];
                for (int i = tid; i < NV4; i += GTH) {
                    float4 v = __ldcs(&xr[i]);
                    unsigned int ks[4] = {f2k(v.x), f2k(v.y), f2k(v.z), f2k(v.w)};
                    #pragma unroll
                    for (int e = 0; e < 4; e++) {
                        unsigned int t1 = ks[e] >> 21, sub = (ks[e] >> 10) & 2047u;
                        if (t1 == b0) atomicAdd(&sm[sub], 1u);
                        if (t1 == b1) atomicAdd(&sm[2048 + sub], 1u);
                    }
                }
            }
            __syncthreads();
            scanloc(sm,        2048, R0 - sp[0], NORANK, 0, wsum, s_out, tid, lane, wid);
            if (tid == 0) { b2s[0] = s_out[0]; p2s[0] = s_out[1]; }
            __syncthreads();
            scanloc(sm + 2048, 2048, R1 - sp[1], NORANK, 0, wsum, s_out, tid, lane, wid);
            if (tid == 0) { b2s[1] = s_out[0]; p2s[1] = s_out[1]; }
            __syncthreads();

            for (int j = tid; j < 2048; j += GTH) sm[j] = 0u;
            __syncthreads();
            {
                const unsigned int t0 = (sb[0] << 11) | b2s[0];
                const unsigned int t1 = (sb[1] << 11) | b2s[1];
                for (int i = tid; i < NV4; i += GTH) {
                    float4 v = __ldcs(&xr[i]);
                    unsigned int ks[4] = {f2k(v.x), f2k(v.y), f2k(v.z), f2k(v.w)};
                    #pragma unroll
                    for (int e = 0; e < 4; e++) {
                        unsigned int tt = ks[e] >> 10, sub = ks[e] & 1023u;
                        if (tt == t0) atomicAdd(&sm[sub], 1u);
                        if (tt == t1) atomicAdd(&sm[1024 + sub], 1u);
                    }
                }
            }
            __syncthreads();
            scanloc(sm,        1024, R0 - sp[0] - p2s[0], NORANK, 0, wsum, s_out, tid, lane, wid);
            if (tid == 0) keyq[0] = (sb[0] << 21) | (b2s[0] << 10) | s_out[0];
            __syncthreads();
            scanloc(sm + 1024, 1024, R1 - sp[1] - p2s[1], NORANK, 0, wsum, s_out, tid, lane, wid);
            if (tid == 0) keyq[1] = (sb[1] << 21) | (b2s[1] << 10) | s_out[0];
            __syncthreads();
        }

        if (tid == 0) {
            double frac = side ? (0.99 * (double)(NPERROW - 1) - 259521.0)
                               : (0.01 * (double)(NPERROW - 1) - 2621.0);
            double v0 = (double)k2f(keyq[0]);
            double v1 = (double)k2f(keyq[1]);
            g_q[row][side] = (float)(v0 + frac * (v1 - v0));
            __threadfence();                       // publish g_q before ready bump
            atomicAdd(&g_qready[row], 1u);
        }
    } else {
        // ==================== GATE CTA: (row, chunk) ====================
        const int task = blockIdx.x - NSEL;
        const int row = task >> 4, chk = task & (CHUNKS - 1);
        const float4* xr   = (const float4*)(x   + (size_t)row * NPERROW) + (size_t)chk * V4C;
        float4*       outr = (float4*)      (out + (size_t)row * NPERROW) + (size_t)chk * V4C;

        if (tid == 0) {
            // writer CTAs (bids 0..255) are wave-1 resident: no deadlock
            while (atomicAdd(&g_qready[row], 0u) < 2u) __nanosleep(128);
            __threadfence();
            s_th[0] = g_q[row][0];
            s_th[1] = g_q[row][1];
        }
        __syncthreads();

        const double i1  = (double)s_th[0];
        const double i99 = (double)s_th[1];
        const float alpha = alpha_p[0];
        const float beta  = beta_p[0];
        const float th = (float)(i1 + (i99 - i1) * (double)alpha);
        const float mask   = (th > 1e-14f) ? 1.0f : 0.0f;
        const float th_new = th * mask + (1.0f - mask);
        const float scale  = beta / th_new;
        const float t      = th * mask;

        const float L2E = 1.4426950408889634f;
        const float a = scale * L2E;      // exp(-(scale*(|x|-t))) = 2^(-a*|x| + b)
        const float b = scale * t * L2E;

        #pragma unroll 4
        for (int i = tid; i < V4C; i += GTH) {
            float4 v = xr[i];
            float4 o;
            o.x = fmaxf(v.x, 0.0f) * rcpa(1.0f + ex2a(fmaf(fabsf(v.x), -a, b)));
            o.y = fmaxf(v.y, 0.0f) * rcpa(1.0f + ex2a(fmaf(fabsf(v.y), -a, b)));
            o.z = fmaxf(v.z, 0.0f) * rcpa(1.0f + ex2a(fmaf(fabsf(v.z), -a, b)));
            o.w = fmaxf(v.w, 0.0f) * rcpa(1.0f + ex2a(fmaf(fabsf(v.w), -a, b)));
            __stcs(&outr[i], o);
        }
    }
}

extern "C" void kernel_launch(void* const* d_in, const int* in_sizes, int n_in,
                              void* d_out, int out_size)
{
    const float* x     = (const float*)d_in[0];
    const float* alpha = (const float*)d_in[1];
    const float* beta  = (const float*)d_in[2];
    float* out = (float*)d_out;

    gather_kernel<<<NROWS * CHUNKS, GTH>>>(x);
    selgate_kernel<<<NSEL + NROWS * CHUNKS, GTH>>>(x, out, alpha, beta);
}

// round 17
// speedup vs baseline: 1.1382x; 1.0268x over previous
#include <cuda_runtime.h>
#include <math.h>

#define NPERROW (512*512)            // 262144
#define NROWS   128
#define NV4     (NPERROW/4)          // 65536
#define FULLM   0xFFFFFFFFu
#define NORANK  0xFFFFFFFFu

#define CHUNKS  16
#define GTH     256
#define V4C     (NV4/CHUNKS)         // 4096 float4 per chunk
#define V4T     (V4C/GTH)            // 16 float4 per thread
#define NW      (GTH/32)             // 8 warps
#define TCAP    24                   // per-thread stage cap (exp ~3)
#define CSEG    1024                 // per-chunk segment cap (exp ~746)
#define MCAP    (CHUNKS*CSEG)        // 16384
#define CCAPS   1536                 // candidate cap (exp ~900)

__device__ unsigned int g_buf[NROWS][MCAP];    // 8 MB scratch
__device__ unsigned int g_ccnt[NROWS][CHUNKS];
__device__ float        g_q[NROWS][2];         // [0]=i1, [1]=i99

// monotone float -> uint key
__device__ __forceinline__ unsigned int f2k(float f) {
    unsigned int u = __float_as_uint(f);
    return u ^ ((unsigned int)((int)u >> 31) | 0x80000000u);
}
__device__ __forceinline__ float k2f(unsigned int k) {
    unsigned int u = (k & 0x80000000u) ? (k ^ 0x80000000u) : ~k;
    return __uint_as_float(u);
}
__device__ __forceinline__ float ex2a(float x){ float r; asm("ex2.approx.ftz.f32 %0, %1;" : "=f"(r) : "f"(x)); return r; }
__device__ __forceinline__ float rcpa(float x){ float r; asm("rcp.approx.ftz.f32 %0, %1;" : "=f"(r) : "f"(x)); return r; }

// ===================== Kernel 1: wide tail gather (R14-proven verbatim) =====================
__global__ __launch_bounds__(GTH)
void gather_kernel(const float* __restrict__ x)
{
    __shared__ unsigned int stage[TCAP * GTH];
    __shared__ unsigned int wsum[NW];
    __shared__ int s_ov;

    const int tid  = threadIdx.x;
    const int lane = tid & 31;
    const int wid  = tid >> 5;
    const int row  = blockIdx.x >> 4;
    const int chk  = blockIdx.x & (CHUNKS - 1);
    const float4* xr = (const float4*)(x + (size_t)row * NPERROW) + (size_t)chk * V4C;

    if (tid == 0) s_ov = 0;
    __syncthreads();

    unsigned int cnt = 0;
    #pragma unroll
    for (int it = 0; it < V4T / 8; it++) {
        float4 v[8];
        #pragma unroll
        for (int s = 0; s < 8; s++)
            v[s] = xr[tid + (it * 8 + s) * GTH];

        #pragma unroll
        for (int s = 0; s < 8; s++) {
            if (fabsf(v[s].x) > 2.0f) { if (cnt < TCAP) stage[cnt * GTH + tid] = f2k(v[s].x); cnt++; }
            if (fabsf(v[s].y) > 2.0f) { if (cnt < TCAP) stage[cnt * GTH + tid] = f2k(v[s].y); cnt++; }
            if (fabsf(v[s].z) > 2.0f) { if (cnt < TCAP) stage[cnt * GTH + tid] = f2k(v[s].z); cnt++; }
            if (fabsf(v[s].w) > 2.0f) { if (cnt < TCAP) stage[cnt * GTH + tid] = f2k(v[s].w); cnt++; }
        }
    }
    if (cnt > TCAP) s_ov = 1;   // benign race; ordered by barriers below

    unsigned int inc = cnt;
    #pragma unroll
    for (int o = 1; o < 32; o <<= 1) {
        unsigned int t = __shfl_up_sync(FULLM, inc, o);
        if (lane >= o) inc += t;
    }
    if (lane == 31) wsum[wid] = inc;
    __syncthreads();
    if (tid < NW) {
        unsigned int w = wsum[tid];
        #pragma unroll
        for (int o = 1; o < NW; o <<= 1) {
            unsigned int t = __shfl_up_sync(0xFFu, w, o);
            if (tid >= o) w += t;
        }
        wsum[tid] = w;
    }
    __syncthreads();

    unsigned int pre   = (wid ? wsum[wid - 1] : 0u) + inc - cnt;
    unsigned int total = wsum[NW - 1];
    int ov = s_ov || (total > CSEG);

    if (!ov) {
        unsigned int* dst = &g_buf[row][chk * CSEG + pre];
        for (unsigned int j = 0; j < cnt; j++) dst[j] = stage[j * GTH + tid];
    }
    if (tid == 0) g_ccnt[row][chk] = ov ? 0xFFFFFFFFu : total;
}

// ===================== Kernel 2: per-(row,side) select, 256 threads =====================

// block scan over h[0..nbins) (nbins multiple of 256); locate lr0 (and lr1 if != NORANK).
// from_top: lr = total - lr_in. Outputs: s_out[0]=bin0,[1]=pre0,[2]=bin1,[3]=pre1,[4]=total.
__device__ void scanloc(unsigned int* h, int nbins,
                        unsigned int lr0_in, unsigned int lr1_in, int from_top,
                        unsigned int* wsum, unsigned int* s_out,
                        int tid, int lane, int wid)
{
    const int bpt = nbins >> 8;
    unsigned int s = 0;
    for (int j = 0; j < bpt; j++) s += h[tid * bpt + j];
    unsigned int inc = s;
    #pragma unroll
    for (int o = 1; o < 32; o <<= 1) {
        unsigned int t = __shfl_up_sync(FULLM, inc, o);
        if (lane >= o) inc += t;
    }
    if (lane == 31) wsum[wid] = inc;
    __syncthreads();
    if (tid < NW) {
        unsigned int w = wsum[tid];
        #pragma unroll
        for (int o = 1; o < NW; o <<= 1) {
            unsigned int t = __shfl_up_sync(0xFFu, w, o);
            if (tid >= o) w += t;
        }
        wsum[tid] = w;
    }
    __syncthreads();
    const unsigned int total = wsum[NW - 1];
    if (tid == 0) s_out[4] = total;
    unsigned int lr0 = from_top ? (total - lr0_in) : lr0_in;
    unsigned int lr1 = (lr1_in == NORANK) ? NORANK : (from_top ? (total - lr1_in) : lr1_in);
    unsigned int run = (wid ? wsum[wid - 1] : 0u) + inc - s;
    for (int j = 0; j < bpt; j++) {
        unsigned int c = h[tid * bpt + j];
        unsigned int b = (unsigned int)(tid * bpt + j);
        if (run <= lr0 && lr0 < run + c) { s_out[0] = b; s_out[1] = run; }
        if (lr1 != NORANK && run <= lr1 && lr1 < run + c) { s_out[2] = b; s_out[3] = run; }
        run += c;
    }
    __syncthreads();
}

__global__ __launch_bounds__(GTH)
void select_kernel(const float* __restrict__ x)
{
    __shared__ unsigned int sm[4096 + CCAPS];   // hist arena + candidates (22.5 KB)
    __shared__ unsigned int wsum[NW];
    __shared__ unsigned int cc[CHUNKS];
    __shared__ unsigned int s_out[5];
    __shared__ unsigned int sb[2], sp[2], b2s[2], p2s[2], keyq[2];
    __shared__ unsigned int s_c;
    __shared__ int s_mode;

    const int tid  = threadIdx.x;
    const int lane = tid & 31;
    const int wid  = tid >> 5;
    const int row  = blockIdx.x >> 1;
    const int side = blockIdx.x & 1;
    const unsigned int base = side ? 0xC0000000u : 0u;

    if (tid < CHUNKS) cc[tid] = g_ccnt[row][tid];
    __syncthreads();
    if (tid == 0) {
        int bad = 0;
        #pragma unroll
        for (int c = 0; c < CHUNKS; c++) if (cc[c] > CSEG) bad = 1;
        s_mode = bad;
    }
    __syncthreads();

    unsigned int lr0 = 0, lr1 = 0;

    if (s_mode == 0) {
        // pass 1: 4096-bin hist over rel>>18 (side keys occupy exactly [0,2^30))
        for (int j = tid; j < 4096; j += GTH) sm[j] = 0u;
        __syncthreads();
        for (int i = tid; i < MCAP; i += GTH) {
            if ((unsigned int)(i & (CSEG - 1)) < cc[i >> 10]) {
                unsigned int k = g_buf[row][i];
                if (side ? (k >= 0x80000000u) : (k < 0x80000000u))
                    atomicAdd(&sm[(k - base) >> 18], 1u);
            }
        }
        __syncthreads();
        scanloc(sm, 4096, side ? 2623u : 2621u, side ? 2622u : 2622u, side,
                wsum, s_out, tid, lane, wid);
        if (tid == 0) { sb[0] = s_out[0]; sp[0] = s_out[1]; sb[1] = s_out[2]; sp[1] = s_out[3]; }
        __syncthreads();
        const unsigned int Mside = s_out[4];
        if (Mside < 2623u) { if (tid == 0) s_mode = 1; }
        __syncthreads();

        if (s_mode == 0) {
            lr0 = side ? (Mside - 2623u) : 2621u;
            lr1 = side ? (Mside - 2622u) : 2622u;

            if (tid == 0) s_c = 0u;
            __syncthreads();
            const unsigned int blo = sb[0], bhi = sb[1];
            for (int i = tid; i < MCAP; i += GTH) {
                if ((unsigned int)(i & (CSEG - 1)) < cc[i >> 10]) {
                    unsigned int k = g_buf[row][i];
                    if (side ? (k >= 0x80000000u) : (k < 0x80000000u)) {
                        unsigned int rel = k - base;
                        unsigned int b = rel >> 18;
                        if (b >= blo && b <= bhi) {
                            unsigned int p = atomicAdd(&s_c, 1u);
                            if (p < CCAPS) sm[4096 + p] = rel;
                        }
                    }
                }
            }
            __syncthreads();
            if (s_c > (unsigned int)CCAPS) { if (tid == 0) s_mode = 1; }
            __syncthreads();
        }

        if (s_mode == 0) {
            const unsigned int nc = s_c;
            unsigned int lrq0 = lr0 - sp[0], lrq1 = lr1 - sp[1];
            #pragma unroll
            for (int q = 0; q < 2; q++) {
                const unsigned int b = sb[q];
                unsigned int lr = q ? lrq1 : lrq0;

                for (int j = tid; j < 1024; j += GTH) sm[j] = 0u;
                __syncthreads();
                for (unsigned int i = tid; i < nc; i += GTH) {
                    unsigned int rel = sm[4096 + i];
                    if ((rel >> 18) == b) atomicAdd(&sm[(rel >> 8) & 1023u], 1u);
                }
                __syncthreads();
                scanloc(sm, 1024, lr, NORANK, 0, wsum, s_out, tid, lane, wid);
                const unsigned int s1 = s_out[0];
                lr -= s_out[1];
                __syncthreads();

                const unsigned int t18 = (b << 10) | s1;
                for (int j = tid; j < 256; j += GTH) sm[j] = 0u;
                __syncthreads();
                for (unsigned int i = tid; i < nc; i += GTH) {
                    unsigned int rel = sm[4096 + i];
                    if ((rel >> 8) == t18) atomicAdd(&sm[rel & 255u], 1u);
                }
                __syncthreads();
                scanloc(sm, 256, lr, NORANK, 0, wsum, s_out, tid, lane, wid);
                if (tid == 0) keyq[q] = base + ((b << 18) | (s1 << 8) | s_out[0]);
                __syncthreads();
            }
        }
    }

    if (s_mode == 1) {
        // exact full-row fallback: 11/11/10-bit radix for this side's 2 ranks
        const float4* xr = (const float4*)(x + (size_t)row * NPERROW);
        const unsigned int R0 = side ? 259521u : 2621u;
        const unsigned int R1 = R0 + 1u;

        for (int j = tid; j < 2048; j += GTH) sm[j] = 0u;
        __syncthreads();
        for (int i = tid; i < NV4; i += GTH) {
            float4 v = __ldcs(&xr[i]);
            atomicAdd(&sm[f2k(v.x) >> 21], 1u);
            atomicAdd(&sm[f2k(v.y) >> 21], 1u);
            atomicAdd(&sm[f2k(v.z) >> 21], 1u);
            atomicAdd(&sm[f2k(v.w) >> 21], 1u);
        }
        __syncthreads();
        scanloc(sm, 2048, R0, R1, 0, wsum, s_out, tid, lane, wid);
        if (tid == 0) { sb[0] = s_out[0]; sp[0] = s_out[1]; sb[1] = s_out[2]; sp[1] = s_out[3]; }
        __syncthreads();

        for (int j = tid; j < 4096; j += GTH) sm[j] = 0u;
        __syncthreads();
        {
            const unsigned int b0 = sb[0], b1 = sb[1];
            for (int i = tid; i < NV4; i += GTH) {
                float4 v = __ldcs(&xr[i]);
                unsigned int ks[4] = {f2k(v.x), f2k(v.y), f2k(v.z), f2k(v.w)};
                #pragma unroll
                for (int e = 0; e < 4; e++) {
                    unsigned int t1 = ks[e] >> 21, sub = (ks[e] >> 10) & 2047u;
                    if (t1 == b0) atomicAdd(&sm[sub], 1u);
                    if (t1 == b1) atomicAdd(&sm[2048 + sub], 1u);
                }
            }
        }
        __syncthreads();
        scanloc(sm,        2048, R0 - sp[0], NORANK, 0, wsum, s_out, tid, lane, wid);
        if (tid == 0) { b2s[0] = s_out[0]; p2s[0] = s_out[1]; }
        __syncthreads();
        scanloc(sm + 2048, 2048, R1 - sp[1], NORANK, 0, wsum, s_out, tid, lane, wid);
        if (tid == 0) { b2s[1] = s_out[0]; p2s[1] = s_out[1]; }
        __syncthreads();

        for (int j = tid; j < 2048; j += GTH) sm[j] = 0u;
        __syncthreads();
        {
            const unsigned int t0 = (sb[0] << 11) | b2s[0];
            const unsigned int t1 = (sb[1] << 11) | b2s[1];
            for (int i = tid; i < NV4; i += GTH) {
                float4 v = __ldcs(&xr[i]);
                unsigned int ks[4] = {f2k(v.x), f2k(v.y), f2k(v.z), f2k(v.w)};
                #pragma unroll
                for (int e = 0; e < 4; e++) {
                    unsigned int tt = ks[e] >> 10, sub = ks[e] & 1023u;
                    if (tt == t0) atomicAdd(&sm[sub], 1u);
                    if (tt == t1) atomicAdd(&sm[1024 + sub], 1u);
                }
            }
        }
        __syncthreads();
        scanloc(sm,        1024, R0 - sp[0] - p2s[0], NORANK, 0, wsum, s_out, tid, lane, wid);
        if (tid == 0) keyq[0] = (sb[0] << 21) | (b2s[0] << 10) | s_out[0];
        __syncthreads();
        scanloc(sm + 1024, 1024, R1 - sp[1] - p2s[1], NORANK, 0, wsum, s_out, tid, lane, wid);
        if (tid == 0) keyq[1] = (sb[1] << 21) | (b2s[1] << 10) | s_out[0];
        __syncthreads();
    }

    if (tid == 0) {
        double frac = side ? (0.99 * (double)(NPERROW - 1) - 259521.0)
                           : (0.01 * (double)(NPERROW - 1) - 2621.0);
        double v0 = (double)k2f(keyq[0]);
        double v1 = (double)k2f(keyq[1]);
        g_q[row][side] = (float)(v0 + frac * (v1 - v0));
    }
}

// ===================== Kernel 3: streaming gate (R14-proven verbatim) =====================
__global__ __launch_bounds__(GTH)
void gate_kernel(const float* __restrict__ x, float* __restrict__ out,
                 const float* __restrict__ alpha_p, const float* __restrict__ beta_p)
{
    const int c   = blockIdx.x;
    const int row = c >> 4;            // CHUNKS = 16
    const int chk = c & 15;
    const float4* xr   = (const float4*)(x   + (size_t)row * NPERROW) + (size_t)chk * V4C;
    float4*       outr = (float4*)      (out + (size_t)row * NPERROW) + (size_t)chk * V4C;

    const double i1  = (double)g_q[row][0];
    const double i99 = (double)g_q[row][1];
    const float alpha = alpha_p[0];
    const float beta  = beta_p[0];
    const float th = (float)(i1 + (i99 - i1) * (double)alpha);
    const float mask   = (th > 1e-14f) ? 1.0f : 0.0f;
    const float th_new = th * mask + (1.0f - mask);
    const float scale  = beta / th_new;
    const float t      = th * mask;

    const float L2E = 1.4426950408889634f;
    const float a = scale * L2E;        // exp(-(scale*(|x|-t))) = 2^(-a*|x| + b)
    const float b = scale * t * L2E;

    #pragma unroll 4
    for (int i = threadIdx.x; i < V4C; i += GTH) {
        float4 v = xr[i];
        float4 o;
        o.x = fmaxf(v.x, 0.0f) * rcpa(1.0f + ex2a(fmaf(fabsf(v.x), -a, b)));
        o.y = fmaxf(v.y, 0.0f) * rcpa(1.0f + ex2a(fmaf(fabsf(v.y), -a, b)));
        o.z = fmaxf(v.z, 0.0f) * rcpa(1.0f + ex2a(fmaf(fabsf(v.z), -a, b)));
        o.w = fmaxf(v.w, 0.0f) * rcpa(1.0f + ex2a(fmaf(fabsf(v.w), -a, b)));
        __stcs(&outr[i], o);
    }
}

extern "C" void kernel_launch(void* const* d_in, const int* in_sizes, int n_in,
                              void* d_out, int out_size)
{
    const float* x     = (const float*)d_in[0];
    const float* alpha = (const float*)d_in[1];
    const float* beta  = (const float*)d_in[2];
    float* out = (float*)d_out;

    gather_kernel<<<NROWS * CHUNKS, GTH>>>(x);
    select_kernel<<<NROWS * 2, GTH>>>(x);
    gate_kernel<<<NROWS * CHUNKS, GTH>>>(x, out, alpha, beta);
}